// round 14
// baseline (speedup 1.0000x reference)
#include <cuda_runtime.h>
#include <cuda_fp16.h>
#include <cmath>
#include <cstdint>

// InstantNGP hash-grid encoder, round 14 = round 8 with paired-lane cell
// loads. One warp per point: lanes 0-11 = (cell level, z-half) pairs (one
// 16B quad each, pair shares a 32B region of the z-major cell table -> the
// two halves coalesce into ONE L1 wavefront), lanes 12-21 = hashed levels
// 6-15 (round-8 body verbatim), lanes 22-31 idle.
//  * levels 0-5: cell-packed fp16 tables, z-major (quads at iz, iz+1
//    adjacent) -> ~1.1 wf per (pt,level) instead of 2.
//  * levels 6-15: fp16x2 hash tables, 4-entry LDG.128 windows; ix%4==3
//    lanes add 4 x 4B gathers (avg 5 loads/level).

#define NGP_L 16
#define NGP_T (1u << 19)
#define NGP_MASK ((1u << 19) - 1u)
#define PRIME_Y 2654435761u
#define PRIME_Z 805459861u

#define N_CELL 6                    // levels 0-5 cell-packed
#define NHASH  (NGP_L - N_CELL)     // 10 hashed levels (6-15)

#define QSCALE   65536.0f
#define QSCALE_I (1.0f / 65536.0f)

// cell-packed l0-5: sum (r+1)^2*(r+2) = 876,868 entries, 16B each (z-major)
#define QCAP 880000
__device__ uint4 g_q[QCAP];

// hashed fp16 tables l6-15: 10 * 2^19 * 4B viewed as quads
#define HCONV_ITEMS (NHASH * (int)(NGP_T / 4))
__device__ uint4 g_ht[NHASH * (NGP_T / 4)];

struct NgpParams {
    float cell[NGP_L];
    int   res[NGP_L];
    int   qoff[N_CELL];
    int   ccum[N_CELL + 1];
};

__device__ __forceinline__ float2 hsel(const uint4& q, unsigned i)
{
    const unsigned v = (i & 2u) ? ((i & 1u) ? q.w : q.z)
                                : ((i & 1u) ? q.y : q.x);
    return __half22float2(*reinterpret_cast<const __half2*>(&v));
}
__device__ __forceinline__ float2 h2f(unsigned v)
{
    return __half22float2(*reinterpret_cast<const __half2*>(&v));
}

// -------- fused precompute: hconv (l6-15) + qpack (l0-5, z-major) -----------
__global__ __launch_bounds__(256)
void ngp_prep_kernel(const float* __restrict__ tables, NgpParams p, int ntot)
{
    const int id = blockIdx.x * blockDim.x + threadIdx.x;
    if (id >= ntot) return;

    if (id < HCONV_ITEMS) {
        const float4* __restrict__ src =
            reinterpret_cast<const float4*>(tables)
            + (size_t)N_CELL * (NGP_T / 2) + (size_t)id * 2;
        const float4 a = __ldg(src);
        const float4 b = __ldg(src + 1);
        const __half2 e0 = __floats2half2_rn(a.x * QSCALE, a.y * QSCALE);
        const __half2 e1 = __floats2half2_rn(a.z * QSCALE, a.w * QSCALE);
        const __half2 e2 = __floats2half2_rn(b.x * QSCALE, b.y * QSCALE);
        const __half2 e3 = __floats2half2_rn(b.z * QSCALE, b.w * QSCALE);
        uint4 q;
        q.x = *reinterpret_cast<const unsigned*>(&e0);
        q.y = *reinterpret_cast<const unsigned*>(&e1);
        q.z = *reinterpret_cast<const unsigned*>(&e2);
        q.w = *reinterpret_cast<const unsigned*>(&e3);
        g_ht[id] = q;
        return;
    }

    int rel = id - HCONV_ITEMS;
    int lvl = 0;
    #pragma unroll
    for (int l = 0; l < N_CELL; l++)
        if (rel >= p.ccum[l] && rel < p.ccum[l + 1]) lvl = l;
    rel -= p.ccum[lvl];

    const int res = p.res[lvl];
    const int D1  = res + 1;
    const int DZ  = res + 2;
    // decode with ix fastest (keeps gather window sharing among lanes)
    const int ix  = rel % D1;
    const int t   = rel / D1;
    const int iy  = t % D1;
    const int iz  = t / D1;          // 0 .. DZ-1

    const unsigned hy0 = (unsigned)iy * PRIME_Y;
    const unsigned hy1 = hy0 + PRIME_Y;
    const unsigned hz  = (unsigned)iz * PRIME_Z;
    const unsigned ux  = (unsigned)ix;

    const float2* __restrict__ tab =
        reinterpret_cast<const float2*>(tables) + (unsigned)lvl * NGP_T;

    const float2 a00 = __ldg(tab + ((ux        ^ hy0 ^ hz) & NGP_MASK));
    const float2 a10 = __ldg(tab + (((ux + 1u) ^ hy0 ^ hz) & NGP_MASK));
    const float2 a01 = __ldg(tab + ((ux        ^ hy1 ^ hz) & NGP_MASK));
    const float2 a11 = __ldg(tab + (((ux + 1u) ^ hy1 ^ hz) & NGP_MASK));

    const __half2 h00 = __floats2half2_rn(a00.x * QSCALE, a00.y * QSCALE);
    const __half2 h10 = __floats2half2_rn(a10.x * QSCALE, a10.y * QSCALE);
    const __half2 h01 = __floats2half2_rn(a01.x * QSCALE, a01.y * QSCALE);
    const __half2 h11 = __floats2half2_rn(a11.x * QSCALE, a11.y * QSCALE);

    uint4 q;
    q.x = *reinterpret_cast<const unsigned*>(&h00);
    q.y = *reinterpret_cast<const unsigned*>(&h10);
    q.z = *reinterpret_cast<const unsigned*>(&h01);
    q.w = *reinterpret_cast<const unsigned*>(&h11);
    // z-major store: quads for (iy,ix,iz) and (iy,ix,iz+1) are adjacent
    g_q[p.qoff[lvl] + (iy * D1 + ix) * DZ + iz] = q;
}

// ---------------- main kernel: one warp per point ---------------------------
__global__ __launch_bounds__(256)
void InstantNGP_kernel(const float* __restrict__ xyz,
                       float* __restrict__ out,
                       NgpParams p, int npts)
{
    const int pt   = (blockIdx.x * blockDim.x + threadIdx.x) >> 5;
    const int lane = threadIdx.x & 31;
    if (pt >= npts || lane >= 22) return;

    const float x = __ldg(xyz + pt * 3 + 0);
    const float y = __ldg(xyz + pt * 3 + 1);
    const float z = __ldg(xyz + pt * 3 + 2);

    // lanes 0-11: level = lane>>1 (cells); lanes 12-21: level = lane-6 (hash)
    const int lvl = (lane < 12) ? (lane >> 1) : (lane - 6);

    const float cell = p.cell[lvl];
    const float ux = __fdiv_rn(x, cell);
    const float uy = __fdiv_rn(y, cell);
    const float uz = __fdiv_rn(z, cell);

    const float fx = floorf(ux), fy = floorf(uy), fz = floorf(uz);
    const float dx = ux - fx,    dy = uy - fy,    dz = uz - fz;

    const unsigned ix = (unsigned)(int)fx;
    const unsigned iy = (unsigned)(int)fy;
    const unsigned iz = (unsigned)(int)fz;

    const float wx0 = 1.0f - dx, wx1 = dx;
    const float wy0 = 1.0f - dy, wy1 = dy;
    const float wz0 = 1.0f - dz, wz1 = dz;

    float c0, c1;
    bool do_store;

    if (lane < 12) {
        // ---- paired-lane cell load: each lane loads ONE quad (its z-half);
        //      the pair's two quads are adjacent 16B -> one wavefront. ----
        const int half = lane & 1;
        const int D1 = p.res[lvl] + 1;
        const int DZ = p.res[lvl] + 2;
        const int qi = p.qoff[lvl]
                     + ((int)iy * D1 + (int)ix) * DZ + (int)iz + half;
        const uint4 qa = __ldg(g_q + qi);

        const float2 a00 = h2f(qa.x), a10 = h2f(qa.y);
        const float2 a01 = h2f(qa.z), a11 = h2f(qa.w);

        const float w00 = wx0 * wy0, w10 = wx1 * wy0;
        const float w01 = wx0 * wy1, w11 = wx1 * wy1;

        float s0 = w00 * a00.x;            float s1 = w00 * a00.y;
        s0 = fmaf(w10, a10.x, s0);         s1 = fmaf(w10, a10.y, s1);
        s0 = fmaf(w01, a01.x, s0);         s1 = fmaf(w01, a01.y, s1);
        s0 = fmaf(w11, a11.x, s0);         s1 = fmaf(w11, a11.y, s1);

        const float wz = half ? wz1 : wz0;
        const float pc0 = wz * s0;
        const float pc1 = wz * s1;
        // combine the two z-halves across the lane pair
        c0 = pc0 + __shfl_xor_sync(0x00000fffu, pc0, 1);
        c1 = pc1 + __shfl_xor_sync(0x00000fffu, pc1, 1);
        do_store = (half == 0);
    } else {
        // ---- hashed: 4 quad loads (+4B extras for ix%4==3 lanes) ----
        const int hl = lvl - N_CELL;
        const unsigned m0 = (iy * PRIME_Y)           ^ (iz * PRIME_Z);
        const unsigned m1 = (iy * PRIME_Y)           ^ (iz * PRIME_Z + PRIME_Z);
        const unsigned m2 = (iy * PRIME_Y + PRIME_Y) ^ (iz * PRIME_Z);
        const unsigned m3 = (iy * PRIME_Y + PRIME_Y) ^ (iz * PRIME_Z + PRIME_Z);
        const unsigned h0 = (ix ^ m0) & NGP_MASK;
        const unsigned h1 = (ix ^ m1) & NGP_MASK;
        const unsigned h2 = (ix ^ m2) & NGP_MASK;
        const unsigned h3 = (ix ^ m3) & NGP_MASK;

        const uint4* __restrict__ ht = g_ht + hl * (NGP_T / 4);
        const uint4 q0 = __ldg(ht + (h0 >> 2));
        const uint4 q1 = __ldg(ht + (h1 >> 2));
        const uint4 q2 = __ldg(ht + (h2 >> 2));
        const uint4 q3 = __ldg(ht + (h3 >> 2));

        const unsigned jx = ix + 1u;
        const bool extra = (ix & 3u) == 3u;
        float2 e4, e5, e6, e7;
        if (extra) {
            const unsigned* __restrict__ ht32 =
                reinterpret_cast<const unsigned*>(g_ht) + hl * NGP_T;
            const unsigned v4 = __ldg(ht32 + ((jx ^ m0) & NGP_MASK));
            const unsigned v5 = __ldg(ht32 + ((jx ^ m1) & NGP_MASK));
            const unsigned v6 = __ldg(ht32 + ((jx ^ m2) & NGP_MASK));
            const unsigned v7 = __ldg(ht32 + ((jx ^ m3) & NGP_MASK));
            e4 = h2f(v4); e5 = h2f(v5); e6 = h2f(v6); e7 = h2f(v7);
        } else {
            e4 = hsel(q0, (jx ^ m0) & 3u);
            e5 = hsel(q1, (jx ^ m1) & 3u);
            e6 = hsel(q2, (jx ^ m2) & 3u);
            e7 = hsel(q3, (jx ^ m3) & 3u);
        }
        const float2 e0 = hsel(q0, h0 & 3u);
        const float2 e1 = hsel(q1, h1 & 3u);
        const float2 e2 = hsel(q2, h2 & 3u);
        const float2 e3 = hsel(q3, h3 & 3u);

        const float w0 = wx0 * wy0 * wz0;
        const float w1 = wx0 * wy0 * wz1;
        const float w2 = wx0 * wy1 * wz0;
        const float w3 = wx0 * wy1 * wz1;
        const float w4 = wx1 * wy0 * wz0;
        const float w5 = wx1 * wy0 * wz1;
        const float w6 = wx1 * wy1 * wz0;
        const float w7 = wx1 * wy1 * wz1;

        c0 = w0 * e0.x;  c1 = w0 * e0.y;
        c0 = fmaf(w1, e1.x, c0);  c1 = fmaf(w1, e1.y, c1);
        c0 = fmaf(w2, e2.x, c0);  c1 = fmaf(w2, e2.y, c1);
        c0 = fmaf(w3, e3.x, c0);  c1 = fmaf(w3, e3.y, c1);
        c0 = fmaf(w4, e4.x, c0);  c1 = fmaf(w4, e4.y, c1);
        c0 = fmaf(w5, e5.x, c0);  c1 = fmaf(w5, e5.y, c1);
        c0 = fmaf(w6, e6.x, c0);  c1 = fmaf(w6, e6.y, c1);
        c0 = fmaf(w7, e7.x, c0);  c1 = fmaf(w7, e7.y, c1);
        do_store = true;
    }

    // single predicated store: 16 lanes -> one 128B output row -> 1 wavefront
    if (do_store)
        reinterpret_cast<float2*>(out)[pt * NGP_L + lvl] =
            make_float2(c0 * QSCALE_I, c1 * QSCALE_I);
}

extern "C" void kernel_launch(void* const* d_in, const int* in_sizes, int n_in,
                              void* d_out, int out_size)
{
    const float* xyz    = (const float*)d_in[0];
    const float* tables = (const float*)d_in[1];
    float* out          = (float*)d_out;
    const int npts = in_sizes[0] / 3;

    // Reference resolution chain, replicated exactly in libm double.
    NgpParams p;
    const double B = std::exp((std::log(2048.0) - std::log(16.0)) / 15.0);
    for (int i = 0; i < NGP_L; i++) {
        double res_d = std::floor(16.0 * std::pow(B, (double)i));
        float resf   = (float)res_d;
        p.cell[i] = 1.0f / resf;
        p.res[i]  = (int)res_d;
    }
    int qoff = 0;
    p.ccum[0] = 0;
    for (int i = 0; i < N_CELL; i++) {
        p.qoff[i] = qoff;
        const int r = p.res[i];
        const int n = (r + 1) * (r + 1) * (r + 2);
        qoff += n;
        p.ccum[i + 1] = p.ccum[i] + n;
    }

    // 1) fused precompute
    {
        const int ntot = HCONV_ITEMS + p.ccum[N_CELL];
        ngp_prep_kernel<<<(ntot + 255) / 256, 256>>>(tables, p, ntot);
    }
    // 2) main encode: one warp per point (8 points per 256-thread block)
    {
        const long long total = (long long)npts * 32;
        const int blocks = (int)((total + 255) / 256);
        InstantNGP_kernel<<<blocks, 256>>>(xyz, out, p, npts);
    }
}

// round 15
// speedup vs baseline: 1.2962x; 1.2962x over previous
#include <cuda_runtime.h>
#include <cuda_fp16.h>
#include <cmath>
#include <cstdint>

// InstantNGP hash-grid encoder, round 15.
// Dense 22-task mapping: gid -> (pt = gid/22, task = gid%22).
//   tasks 0-11 : cell levels 0-5, one z-half quad each (z-major table, the
//                pair's two quads are adjacent 16B -> ONE L1 wavefront for
//                both); combine via shfl_xor(1) (pairs are always adjacent
//                lanes and never straddle a warp: pt*22 and task are even).
//   tasks 12-21: hashed levels 6-15, round-8 body verbatim
//                (4 quad loads + 4x4B extras for ix%4==3; avg 5 wf).
// No idle lanes (npts*22 threads exactly).

#define NGP_L 16
#define NGP_T (1u << 19)
#define NGP_MASK ((1u << 19) - 1u)
#define PRIME_Y 2654435761u
#define PRIME_Z 805459861u

#define N_CELL 6                    // levels 0-5 cell-packed
#define NHASH  (NGP_L - N_CELL)     // 10 hashed levels (6-15)
#define TASKS  22                   // 12 cell halves + 10 hashed

#define QSCALE   65536.0f
#define QSCALE_I (1.0f / 65536.0f)

// cell-packed l0-5: sum (r+1)^2*(r+2) = 876,868 entries, 16B each (z-major)
#define QCAP 880000
__device__ uint4 g_q[QCAP];

// hashed fp16 tables l6-15: 10 * 2^19 * 4B viewed as quads
#define HCONV_ITEMS (NHASH * (int)(NGP_T / 4))
__device__ uint4 g_ht[NHASH * (NGP_T / 4)];

struct NgpParams {
    float cell[NGP_L];
    int   res[NGP_L];
    int   qoff[N_CELL];
    int   ccum[N_CELL + 1];
};

__device__ __forceinline__ float2 hsel(const uint4& q, unsigned i)
{
    const unsigned v = (i & 2u) ? ((i & 1u) ? q.w : q.z)
                                : ((i & 1u) ? q.y : q.x);
    return __half22float2(*reinterpret_cast<const __half2*>(&v));
}
__device__ __forceinline__ float2 h2f(unsigned v)
{
    return __half22float2(*reinterpret_cast<const __half2*>(&v));
}

// -------- fused precompute: hconv (l6-15) + qpack (l0-5, z-major) -----------
__global__ __launch_bounds__(256)
void ngp_prep_kernel(const float* __restrict__ tables, NgpParams p, int ntot)
{
    const int id = blockIdx.x * blockDim.x + threadIdx.x;
    if (id >= ntot) return;

    if (id < HCONV_ITEMS) {
        const float4* __restrict__ src =
            reinterpret_cast<const float4*>(tables)
            + (size_t)N_CELL * (NGP_T / 2) + (size_t)id * 2;
        const float4 a = __ldg(src);
        const float4 b = __ldg(src + 1);
        const __half2 e0 = __floats2half2_rn(a.x * QSCALE, a.y * QSCALE);
        const __half2 e1 = __floats2half2_rn(a.z * QSCALE, a.w * QSCALE);
        const __half2 e2 = __floats2half2_rn(b.x * QSCALE, b.y * QSCALE);
        const __half2 e3 = __floats2half2_rn(b.z * QSCALE, b.w * QSCALE);
        uint4 q;
        q.x = *reinterpret_cast<const unsigned*>(&e0);
        q.y = *reinterpret_cast<const unsigned*>(&e1);
        q.z = *reinterpret_cast<const unsigned*>(&e2);
        q.w = *reinterpret_cast<const unsigned*>(&e3);
        g_ht[id] = q;
        return;
    }

    int rel = id - HCONV_ITEMS;
    int lvl = 0;
    #pragma unroll
    for (int l = 0; l < N_CELL; l++)
        if (rel >= p.ccum[l] && rel < p.ccum[l + 1]) lvl = l;
    rel -= p.ccum[lvl];

    const int res = p.res[lvl];
    const int D1  = res + 1;
    const int DZ  = res + 2;
    const int ix  = rel % D1;        // ix fastest: gather window sharing
    const int t   = rel / D1;
    const int iy  = t % D1;
    const int iz  = t / D1;          // 0 .. DZ-1

    const unsigned hy0 = (unsigned)iy * PRIME_Y;
    const unsigned hy1 = hy0 + PRIME_Y;
    const unsigned hz  = (unsigned)iz * PRIME_Z;
    const unsigned ux  = (unsigned)ix;

    const float2* __restrict__ tab =
        reinterpret_cast<const float2*>(tables) + (unsigned)lvl * NGP_T;

    const float2 a00 = __ldg(tab + ((ux        ^ hy0 ^ hz) & NGP_MASK));
    const float2 a10 = __ldg(tab + (((ux + 1u) ^ hy0 ^ hz) & NGP_MASK));
    const float2 a01 = __ldg(tab + ((ux        ^ hy1 ^ hz) & NGP_MASK));
    const float2 a11 = __ldg(tab + (((ux + 1u) ^ hy1 ^ hz) & NGP_MASK));

    const __half2 h00 = __floats2half2_rn(a00.x * QSCALE, a00.y * QSCALE);
    const __half2 h10 = __floats2half2_rn(a10.x * QSCALE, a10.y * QSCALE);
    const __half2 h01 = __floats2half2_rn(a01.x * QSCALE, a01.y * QSCALE);
    const __half2 h11 = __floats2half2_rn(a11.x * QSCALE, a11.y * QSCALE);

    uint4 q;
    q.x = *reinterpret_cast<const unsigned*>(&h00);
    q.y = *reinterpret_cast<const unsigned*>(&h10);
    q.z = *reinterpret_cast<const unsigned*>(&h01);
    q.w = *reinterpret_cast<const unsigned*>(&h11);
    // z-major: quads for (iy,ix,iz) and (iy,ix,iz+1) are adjacent 16B
    g_q[p.qoff[lvl] + (iy * D1 + ix) * DZ + iz] = q;
}

// ---------------- main kernel: dense 22-task mapping ------------------------
__global__ __launch_bounds__(256)
void InstantNGP_kernel(const float* __restrict__ xyz,
                       float* __restrict__ out,
                       NgpParams p, int npts)
{
    const int gid  = blockIdx.x * blockDim.x + threadIdx.x;
    int pt   = gid / TASKS;
    const int task = gid - pt * TASKS;
    const bool live = (pt < npts);
    if (!live) pt = npts - 1;            // keep lanes alive for ballot/shfl

    const bool is_cell = (task < 12);
    const unsigned cellmask = __ballot_sync(0xffffffffu, is_cell);
    const int lvl = is_cell ? (task >> 1) : (task - 6);

    const float x = __ldg(xyz + pt * 3 + 0);
    const float y = __ldg(xyz + pt * 3 + 1);
    const float z = __ldg(xyz + pt * 3 + 2);

    const float cell = p.cell[lvl];
    const float ux = __fdiv_rn(x, cell);
    const float uy = __fdiv_rn(y, cell);
    const float uz = __fdiv_rn(z, cell);

    const float fx = floorf(ux), fy = floorf(uy), fz = floorf(uz);
    const float dx = ux - fx,    dy = uy - fy,    dz = uz - fz;

    const unsigned ix = (unsigned)(int)fx;
    const unsigned iy = (unsigned)(int)fy;
    const unsigned iz = (unsigned)(int)fz;

    const float wx0 = 1.0f - dx, wx1 = dx;
    const float wy0 = 1.0f - dy, wy1 = dy;
    const float wz0 = 1.0f - dz, wz1 = dz;

    float c0, c1;
    bool do_store;

    if (is_cell) {
        // ---- paired-lane cell: one quad per lane; the pair's quads are
        //      adjacent 16B in the z-major table -> one wavefront. ----
        const int half = task & 1;
        const int D1 = p.res[lvl] + 1;
        const int DZ = p.res[lvl] + 2;
        const int qi = p.qoff[lvl]
                     + ((int)iy * D1 + (int)ix) * DZ + (int)iz + half;
        const uint4 qa = __ldg(g_q + qi);

        const float2 a00 = h2f(qa.x), a10 = h2f(qa.y);
        const float2 a01 = h2f(qa.z), a11 = h2f(qa.w);

        const float w00 = wx0 * wy0, w10 = wx1 * wy0;
        const float w01 = wx0 * wy1, w11 = wx1 * wy1;

        float s0 = w00 * a00.x;            float s1 = w00 * a00.y;
        s0 = fmaf(w10, a10.x, s0);         s1 = fmaf(w10, a10.y, s1);
        s0 = fmaf(w01, a01.x, s0);         s1 = fmaf(w01, a01.y, s1);
        s0 = fmaf(w11, a11.x, s0);         s1 = fmaf(w11, a11.y, s1);

        const float wz = half ? wz1 : wz0;
        const float pc0 = wz * s0;
        const float pc1 = wz * s1;
        // combine z-halves across the adjacent lane pair (same arithmetic
        // as round 8's wz0*s + wz1*t: mul, mul, add)
        c0 = pc0 + __shfl_xor_sync(cellmask, pc0, 1);
        c1 = pc1 + __shfl_xor_sync(cellmask, pc1, 1);
        do_store = (half == 0) && live;
    } else {
        // ---- hashed: 4 quad loads (+4B extras for ix%4==3 lanes) ----
        const int hl = lvl - N_CELL;
        const unsigned m0 = (iy * PRIME_Y)           ^ (iz * PRIME_Z);
        const unsigned m1 = (iy * PRIME_Y)           ^ (iz * PRIME_Z + PRIME_Z);
        const unsigned m2 = (iy * PRIME_Y + PRIME_Y) ^ (iz * PRIME_Z);
        const unsigned m3 = (iy * PRIME_Y + PRIME_Y) ^ (iz * PRIME_Z + PRIME_Z);
        const unsigned h0 = (ix ^ m0) & NGP_MASK;
        const unsigned h1 = (ix ^ m1) & NGP_MASK;
        const unsigned h2 = (ix ^ m2) & NGP_MASK;
        const unsigned h3 = (ix ^ m3) & NGP_MASK;

        const uint4* __restrict__ ht = g_ht + hl * (NGP_T / 4);
        const uint4 q0 = __ldg(ht + (h0 >> 2));
        const uint4 q1 = __ldg(ht + (h1 >> 2));
        const uint4 q2 = __ldg(ht + (h2 >> 2));
        const uint4 q3 = __ldg(ht + (h3 >> 2));

        const unsigned jx = ix + 1u;
        const bool extra = (ix & 3u) == 3u;
        float2 e4, e5, e6, e7;
        if (extra) {
            const unsigned* __restrict__ ht32 =
                reinterpret_cast<const unsigned*>(g_ht) + hl * NGP_T;
            const unsigned v4 = __ldg(ht32 + ((jx ^ m0) & NGP_MASK));
            const unsigned v5 = __ldg(ht32 + ((jx ^ m1) & NGP_MASK));
            const unsigned v6 = __ldg(ht32 + ((jx ^ m2) & NGP_MASK));
            const unsigned v7 = __ldg(ht32 + ((jx ^ m3) & NGP_MASK));
            e4 = h2f(v4); e5 = h2f(v5); e6 = h2f(v6); e7 = h2f(v7);
        } else {
            e4 = hsel(q0, (jx ^ m0) & 3u);
            e5 = hsel(q1, (jx ^ m1) & 3u);
            e6 = hsel(q2, (jx ^ m2) & 3u);
            e7 = hsel(q3, (jx ^ m3) & 3u);
        }
        const float2 e0 = hsel(q0, h0 & 3u);
        const float2 e1 = hsel(q1, h1 & 3u);
        const float2 e2 = hsel(q2, h2 & 3u);
        const float2 e3 = hsel(q3, h3 & 3u);

        const float w0 = wx0 * wy0 * wz0;
        const float w1 = wx0 * wy0 * wz1;
        const float w2 = wx0 * wy1 * wz0;
        const float w3 = wx0 * wy1 * wz1;
        const float w4 = wx1 * wy0 * wz0;
        const float w5 = wx1 * wy0 * wz1;
        const float w6 = wx1 * wy1 * wz0;
        const float w7 = wx1 * wy1 * wz1;

        c0 = w0 * e0.x;  c1 = w0 * e0.y;
        c0 = fmaf(w1, e1.x, c0);  c1 = fmaf(w1, e1.y, c1);
        c0 = fmaf(w2, e2.x, c0);  c1 = fmaf(w2, e2.y, c1);
        c0 = fmaf(w3, e3.x, c0);  c1 = fmaf(w3, e3.y, c1);
        c0 = fmaf(w4, e4.x, c0);  c1 = fmaf(w4, e4.y, c1);
        c0 = fmaf(w5, e5.x, c0);  c1 = fmaf(w5, e5.y, c1);
        c0 = fmaf(w6, e6.x, c0);  c1 = fmaf(w6, e6.y, c1);
        c0 = fmaf(w7, e7.x, c0);  c1 = fmaf(w7, e7.y, c1);
        do_store = live;
    }

    if (do_store)
        reinterpret_cast<float2*>(out)[pt * NGP_L + lvl] =
            make_float2(c0 * QSCALE_I, c1 * QSCALE_I);
}

extern "C" void kernel_launch(void* const* d_in, const int* in_sizes, int n_in,
                              void* d_out, int out_size)
{
    const float* xyz    = (const float*)d_in[0];
    const float* tables = (const float*)d_in[1];
    float* out          = (float*)d_out;
    const int npts = in_sizes[0] / 3;

    // Reference resolution chain, replicated exactly in libm double.
    NgpParams p;
    const double B = std::exp((std::log(2048.0) - std::log(16.0)) / 15.0);
    for (int i = 0; i < NGP_L; i++) {
        double res_d = std::floor(16.0 * std::pow(B, (double)i));
        float resf   = (float)res_d;
        p.cell[i] = 1.0f / resf;
        p.res[i]  = (int)res_d;
    }
    int qoff = 0;
    p.ccum[0] = 0;
    for (int i = 0; i < N_CELL; i++) {
        p.qoff[i] = qoff;
        const int r = p.res[i];
        const int n = (r + 1) * (r + 1) * (r + 2);
        qoff += n;
        p.ccum[i + 1] = p.ccum[i] + n;
    }

    // 1) fused precompute
    {
        const int ntot = HCONV_ITEMS + p.ccum[N_CELL];
        ngp_prep_kernel<<<(ntot + 255) / 256, 256>>>(tables, p, ntot);
    }
    // 2) main encode: 22 tasks per point, dense mapping
    {
        const long long total = (long long)npts * TASKS;
        const int blocks = (int)((total + 255) / 256);
        InstantNGP_kernel<<<blocks, 256>>>(xyz, out, p, npts);
    }
}